// round 8
// baseline (speedup 1.0000x reference)
#include <cuda_runtime.h>

#define Tv 1000
#define Dv 1024
#define NCHUNK 125            // 125 chunks x 8 rows = 1000 t-rows
#define NBLK (NCHUNK * 8)     // 1000 blocks, guaranteed co-resident at occ 8

// Scratch (__device__ globals per allocation rules)
__device__ float g_part[NCHUNK * 8 * 1024];  // per-chunk partial t-sums
__device__ float g_vsump[16 * 8 * 64];       // 16 j-slice partials of vsum
__device__ float g_row[8 * 1024];            // per-batch output row
__device__ unsigned int g_barA, g_barB, g_barC, g_done;

static __device__ __forceinline__ unsigned int vload(const unsigned int* p) {
    return *(const volatile unsigned int*)p;
}

// ---------------------------------------------------------------------------
// Single fused kernel. grid (125, 8), 256 threads, 8 blocks/SM guaranteed.
//   A: per-chunk t-sum of x (8 x LDG.128 per thread)        [all 1000 blocks]
//   B: vsum j-slice GEMV (reduce partials, x Wv)            [blocks 0..127]
//   C: row GEMV (folded Wo) -> g_row                        [blocks 0..31]
//   D: broadcast g_row to out (8 x STG.128 per thread)      [all 1000 blocks]
// ---------------------------------------------------------------------------
__global__ void __launch_bounds__(256, 8)
fused_kernel(const float* __restrict__ x,  const float* __restrict__ Wv,
             const float* __restrict__ bv, const float* __restrict__ Wo,
             const float* __restrict__ bo, float* __restrict__ out)
{
    __shared__ float s_xr[4][64];
    __shared__ float s_xs[64];
    __shared__ float s_p[4][64];
    __shared__ float s_vs[8 * 64];
    __shared__ float s_part[8][8][32];

    const int chunk = blockIdx.x;              // 0..124
    const int b     = blockIdx.y;              // 0..7
    const int bid   = b * NCHUNK + chunk;      // 0..999
    const int tid   = threadIdx.x;

    // ---------------- Phase A: xsum chunk ----------------
    {
        const int j4 = tid << 2;
        const float4* xp = (const float4*)(x + ((size_t)b * Tv + chunk * 8) * Dv + j4);
        float4 v0 = xp[0 * 256], v1 = xp[1 * 256], v2 = xp[2 * 256], v3 = xp[3 * 256];
        float4 acc;
        acc.x = (v0.x + v1.x) + (v2.x + v3.x);
        acc.y = (v0.y + v1.y) + (v2.y + v3.y);
        acc.z = (v0.z + v1.z) + (v2.z + v3.z);
        acc.w = (v0.w + v1.w) + (v2.w + v3.w);
        float4 v4 = xp[4 * 256], v5 = xp[5 * 256], v6 = xp[6 * 256], v7 = xp[7 * 256];
        acc.x += (v4.x + v5.x) + (v6.x + v7.x);
        acc.y += (v4.y + v5.y) + (v6.y + v7.y);
        acc.z += (v4.z + v5.z) + (v6.z + v7.z);
        acc.w += (v4.w + v5.w) + (v6.w + v7.w);
        *(float4*)(g_part + ((size_t)(chunk * 8 + b)) * Dv + j4) = acc;
    }
    __threadfence();
    __syncthreads();
    if (tid == 0) atomicAdd(&g_barA, 1u);

    // ---------------- Phase B: vsum j-slice (blocks 0..127) ----------------
    if (bid < 128) {
        if (tid == 0) { while (vload(&g_barA) < NBLK) __nanosleep(64); }
        __syncthreads();

        const int vb  = bid & 7;     // batch
        const int jb  = bid >> 3;    // j-slice 0..15
        const int j   = tid & 63;
        const int seg = tid >> 6;    // 0..3
        const int jg  = jb * 64;

        {   // reduce 125 chunk-partials (segments: 31/31/31/32)
            const int c0 = seg * 31;
            const int cn = (seg == 3) ? 32 : 31;
            float s = 0.f;
            #pragma unroll 31
            for (int c = 0; c < cn; c++)
                s += g_part[((size_t)((c0 + c) * 8 + vb)) * Dv + jg + j];
            s_xr[seg][j] = s;
        }
        __syncthreads();
        if (seg == 0)
            s_xs[j] = s_xr[0][j] + s_xr[1][j] + s_xr[2][j] + s_xr[3][j];
        __syncthreads();

        {   // GEMV 64 j x 64 d
            float acc = 0.f;
            #pragma unroll
            for (int jj = 0; jj < 16; jj++) {
                int jl = seg * 16 + jj;
                acc += s_xs[jl] * Wv[(size_t)(jg + jl) * 64 + j];
            }
            s_p[seg][j] = acc;
        }
        __syncthreads();
        if (seg == 0)
            g_vsump[(jb * 8 + vb) * 64 + j] = s_p[0][j] + s_p[1][j] + s_p[2][j] + s_p[3][j];
        __threadfence();
        __syncthreads();
        if (tid == 0) atomicAdd(&g_barB, 1u);
    }

    // ---------------- Phase C: row GEMV (blocks 0..31) ----------------
    if (bid < 32) {
        if (tid == 0) { while (vload(&g_barB) < 128) __nanosleep(64); }
        __syncthreads();

        const int n0   = bid * 32;
        const int lane = tid & 31;
        const int wid  = tid >> 5;
        const int n    = n0 + lane;

        #pragma unroll
        for (int i = tid; i < 512; i += 256) {
            int d = i & 63;
            float s = (float)Tv * bv[d];
            #pragma unroll
            for (int jb2 = 0; jb2 < 16; jb2++)
                s += g_vsump[jb2 * 512 + i];
            s_vs[i] = s;
        }
        __syncthreads();

        float acc[8] = {};
        const int mbase = wid * 128;
        #pragma unroll 8
        for (int mm = 0; mm < 64; mm++) {
            float w1 = Wo[(size_t)(mbase + mm) * Dv + n];
            float w2 = Wo[(size_t)(mbase + mm + 64) * Dv + n];
            float w  = w1 + w2;
            #pragma unroll
            for (int bb = 0; bb < 8; bb++)
                acc[bb] = fmaf(s_vs[bb * 64 + mm], w, acc[bb]);
        }
        #pragma unroll
        for (int bb = 0; bb < 8; bb++)
            s_part[wid][bb][lane] = acc[bb];
        __syncthreads();

        {
            int bb = wid;
            float s = bo[n];
            #pragma unroll
            for (int w = 0; w < 8; w++)
                s += s_part[w][bb][lane];
            g_row[bb * Dv + n] = s;
        }
        __threadfence();
        __syncthreads();
        if (tid == 0) atomicAdd(&g_barC, 1u);
    }

    // ---------------- Phase D: broadcast write (all blocks) ----------------
    if (tid == 0) { while (vload(&g_barC) < 32) __nanosleep(64); }
    __syncthreads();

    {
        float4 v = ((const float4*)g_row)[b * 256 + tid];
        float4* op = (float4*)out + ((size_t)b * Tv + chunk * 8) * 256 + tid;
        op[0 * 256] = v;  op[1 * 256] = v;  op[2 * 256] = v;  op[3 * 256] = v;
        op[4 * 256] = v;  op[5 * 256] = v;  op[6 * 256] = v;  op[7 * 256] = v;
    }

    // ---------------- Epilogue: reset barriers for next replay ----------------
    __syncthreads();
    if (tid == 0) {
        unsigned int d = atomicAdd(&g_done, 1u);
        if (d == NBLK - 1) {
            atomicExch(&g_barA, 0u);
            atomicExch(&g_barB, 0u);
            atomicExch(&g_barC, 0u);
            atomicExch(&g_done, 0u);
        }
    }
}

// ---------------------------------------------------------------------------
extern "C" void kernel_launch(void* const* d_in, const int* in_sizes, int n_in,
                              void* d_out, int out_size)
{
    const float* x  = (const float*)d_in[0];
    const float* Wv = (const float*)d_in[5];
    const float* bv = (const float*)d_in[6];
    const float* Wo = (const float*)d_in[7];
    const float* bo = (const float*)d_in[8];
    float* out = (float*)d_out;

    fused_kernel<<<dim3(NCHUNK, 8), 256>>>(x, Wv, bv, Wo, bo, out);
}

// round 9
// speedup vs baseline: 1.4564x; 1.4564x over previous
#include <cuda_runtime.h>

#define Tv 1000
#define Dv 1024
#define NCHUNK 125   // 125 chunks x 8 rows = 1000

// Scratch (__device__ globals per allocation rules)
__device__ float g_part[NCHUNK * 8 * 1024];  // per-chunk partial t-sums
__device__ float g_vsump[16 * 8 * 64];       // 16 j-slice partials of vsum
__device__ float g_row[8 * 1024];            // per-batch output row
__device__ unsigned int g_bar, g_done;

static __device__ __forceinline__ unsigned int vload(const unsigned int* p) {
    return *(const volatile unsigned int*)p;
}

// ---------------------------------------------------------------------------
// 1) Partial sums over t: grid (125, 8), 256 threads.
//    occ hint 4 -> ~64-reg budget so all 8 LDG.128 can be in flight (MLP=8).
// ---------------------------------------------------------------------------
__global__ void __launch_bounds__(256, 4)
xsum_part_kernel(const float* __restrict__ x)
{
    const int chunk = blockIdx.x;
    const int b     = blockIdx.y;
    const int j4    = threadIdx.x << 2;

    const float4* xp = (const float4*)(x + ((size_t)b * Tv + chunk * 8) * Dv + j4);
    float4 v0 = xp[0 * 256], v1 = xp[1 * 256], v2 = xp[2 * 256], v3 = xp[3 * 256];
    float4 v4 = xp[4 * 256], v5 = xp[5 * 256], v6 = xp[6 * 256], v7 = xp[7 * 256];

    float4 acc;
    acc.x = ((v0.x + v1.x) + (v2.x + v3.x)) + ((v4.x + v5.x) + (v6.x + v7.x));
    acc.y = ((v0.y + v1.y) + (v2.y + v3.y)) + ((v4.y + v5.y) + (v6.y + v7.y));
    acc.z = ((v0.z + v1.z) + (v2.z + v3.z)) + ((v4.z + v5.z) + (v6.z + v7.z));
    acc.w = ((v0.w + v1.w) + (v2.w + v3.w)) + ((v4.w + v5.w) + (v6.w + v7.w));

    *(float4*)(g_part + ((size_t)(chunk * 8 + b)) * Dv + j4) = acc;
}

// ---------------------------------------------------------------------------
// 2) Fused vsum + row. grid 128 blocks (all co-resident on 148 SMs), 256 thr.
//    Phase B: block (jb = bid>>3, vb = bid&7) reduces its 64-wide j slice of
//             the 125 chunk-partials, GEMVs vs Wv -> g_vsump.
//    barrier(128)
//    Phase C: blocks 0..31 do the folded-Wo row GEMV -> g_row.
// ---------------------------------------------------------------------------
__global__ void __launch_bounds__(256)
vsum_row_kernel(const float* __restrict__ Wv, const float* __restrict__ bv,
                const float* __restrict__ Wo, const float* __restrict__ bo)
{
    __shared__ float s_xr[4][64];
    __shared__ float s_xs[64];
    __shared__ float s_p[4][64];
    __shared__ float s_vs[8 * 64];
    __shared__ float s_part[8][8][32];

    const int bid = blockIdx.x;   // 0..127
    const int tid = threadIdx.x;

    // ---- Phase B: vsum j-slice ----
    {
        const int vb  = bid & 7;
        const int jb  = bid >> 3;
        const int j   = tid & 63;
        const int seg = tid >> 6;
        const int jg  = jb * 64;

        const int c0 = seg * 31;
        const int cn = (seg == 3) ? 32 : 31;
        float s = 0.f;
        #pragma unroll 31
        for (int c = 0; c < cn; c++)
            s += g_part[((size_t)((c0 + c) * 8 + vb)) * Dv + jg + j];
        s_xr[seg][j] = s;
        __syncthreads();
        if (seg == 0)
            s_xs[j] = s_xr[0][j] + s_xr[1][j] + s_xr[2][j] + s_xr[3][j];
        __syncthreads();

        float acc = 0.f;
        #pragma unroll
        for (int jj = 0; jj < 16; jj++) {
            int jl = seg * 16 + jj;
            acc += s_xs[jl] * Wv[(size_t)(jg + jl) * 64 + j];
        }
        s_p[seg][j] = acc;
        __syncthreads();
        if (seg == 0)
            g_vsump[(jb * 8 + vb) * 64 + j] =
                s_p[0][j] + s_p[1][j] + s_p[2][j] + s_p[3][j];
    }
    __threadfence();
    __syncthreads();
    if (tid == 0) atomicAdd(&g_bar, 1u);

    // ---- Phase C: row GEMV (blocks 0..31) ----
    if (bid < 32) {
        if (tid == 0) { while (vload(&g_bar) < 128) __nanosleep(32); }
        __syncthreads();

        const int n0   = bid * 32;
        const int lane = tid & 31;
        const int wid  = tid >> 5;
        const int n    = n0 + lane;

        #pragma unroll
        for (int i = tid; i < 512; i += 256) {
            int d = i & 63;
            float s = (float)Tv * bv[d];
            #pragma unroll
            for (int jb = 0; jb < 16; jb++)
                s += g_vsump[jb * 512 + i];
            s_vs[i] = s;
        }
        __syncthreads();

        float acc[8] = {};
        const int mbase = wid * 128;
        #pragma unroll 8
        for (int mm = 0; mm < 64; mm++) {
            float w1 = Wo[(size_t)(mbase + mm) * Dv + n];
            float w2 = Wo[(size_t)(mbase + mm + 64) * Dv + n];
            float w  = w1 + w2;
            #pragma unroll
            for (int bb = 0; bb < 8; bb++)
                acc[bb] = fmaf(s_vs[bb * 64 + mm], w, acc[bb]);
        }
        #pragma unroll
        for (int bb = 0; bb < 8; bb++)
            s_part[wid][bb][lane] = acc[bb];
        __syncthreads();

        {
            int bb = wid;
            float s = bo[n];
            #pragma unroll
            for (int w = 0; w < 8; w++)
                s += s_part[w][bb][lane];
            g_row[bb * Dv + n] = s;
        }
    }

    // ---- Reset barrier for next graph replay ----
    __syncthreads();
    if (tid == 0) {
        unsigned int d = atomicAdd(&g_done, 1u);
        if (d == 127u) {           // last block: all spins have passed
            atomicExch(&g_bar, 0u);
            atomicExch(&g_done, 0u);
        }
    }
}

// ---------------------------------------------------------------------------
// 3) Broadcast: grid (125, 8), 256 threads. One float4/thread from g_row,
//    8 fully-unrolled STG.128 rows.
// ---------------------------------------------------------------------------
__global__ void __launch_bounds__(256)
bcast_kernel(float* __restrict__ out)
{
    const int chunk = blockIdx.x;
    const int b     = blockIdx.y;

    float4 v = ((const float4*)g_row)[b * 256 + threadIdx.x];
    float4* op = (float4*)out + ((size_t)b * Tv + chunk * 8) * 256 + threadIdx.x;
    op[0 * 256] = v;  op[1 * 256] = v;  op[2 * 256] = v;  op[3 * 256] = v;
    op[4 * 256] = v;  op[5 * 256] = v;  op[6 * 256] = v;  op[7 * 256] = v;
}

// ---------------------------------------------------------------------------
extern "C" void kernel_launch(void* const* d_in, const int* in_sizes, int n_in,
                              void* d_out, int out_size)
{
    const float* x  = (const float*)d_in[0];
    const float* Wv = (const float*)d_in[5];
    const float* bv = (const float*)d_in[6];
    const float* Wo = (const float*)d_in[7];
    const float* bo = (const float*)d_in[8];
    float* out = (float*)d_out;

    xsum_part_kernel<<<dim3(NCHUNK, 8), 256>>>(x);
    vsum_row_kernel<<<128, 256>>>(Wv, bv, Wo, bo);
    bcast_kernel<<<dim3(NCHUNK, 8), 256>>>(out);
}

// round 10
// speedup vs baseline: 1.7588x; 1.2076x over previous
#include <cuda_runtime.h>

#define Tv 1000
#define Dv 1024
#define NCHUNK 125   // 125 chunks x 8 rows = 1000

// Scratch (__device__ globals per allocation rules)
__device__ float g_part[NCHUNK * 8 * 1024];  // per-chunk partial t-sums
__device__ float g_vsump[16 * 8 * 64];       // 16 j-slice partials of vsum
__device__ float g_row[8 * 1024];            // per-batch output row

// Streaming (evict-first) 128-bit store: keep `out` from polluting L2.
static __device__ __forceinline__ void stcs128(float4* p, float4 v) {
    asm volatile("st.global.cs.v4.f32 [%0], {%1, %2, %3, %4};"
                 :: "l"(p), "f"(v.x), "f"(v.y), "f"(v.z), "f"(v.w) : "memory");
}

// ---------------------------------------------------------------------------
// 1) Partial sums over t: grid (125, 8), 256 threads, 8 batched LDG.128.
// ---------------------------------------------------------------------------
__global__ void __launch_bounds__(256)
xsum_part_kernel(const float* __restrict__ x)
{
    const int chunk = blockIdx.x;
    const int b     = blockIdx.y;
    const int j4    = threadIdx.x << 2;

    const float4* xp = (const float4*)(x + ((size_t)b * Tv + chunk * 8) * Dv + j4);
    float4 v0 = xp[0 * 256], v1 = xp[1 * 256], v2 = xp[2 * 256], v3 = xp[3 * 256];
    float4 v4 = xp[4 * 256], v5 = xp[5 * 256], v6 = xp[6 * 256], v7 = xp[7 * 256];

    float4 acc;
    acc.x = ((v0.x + v1.x) + (v2.x + v3.x)) + ((v4.x + v5.x) + (v6.x + v7.x));
    acc.y = ((v0.y + v1.y) + (v2.y + v3.y)) + ((v4.y + v5.y) + (v6.y + v7.y));
    acc.z = ((v0.z + v1.z) + (v2.z + v3.z)) + ((v4.z + v5.z) + (v6.z + v7.z));
    acc.w = ((v0.w + v1.w) + (v2.w + v3.w)) + ((v4.w + v5.w) + (v6.w + v7.w));

    *(float4*)(g_part + ((size_t)(chunk * 8 + b)) * Dv + j4) = acc;
}

// ---------------------------------------------------------------------------
// 2) vsum partials: grid (8 b, 16 jb). Each block owns a 64-wide j slice.
// ---------------------------------------------------------------------------
__global__ void __launch_bounds__(256)
vsum_part_kernel(const float* __restrict__ Wv)
{
    __shared__ float xr[4][64];
    __shared__ float xs[64];
    __shared__ float p[4][64];
    const int b   = blockIdx.x;
    const int jb  = blockIdx.y;
    const int tid = threadIdx.x;
    const int j   = tid & 63;
    const int seg = tid >> 6;
    const int jg  = jb * 64;

    {
        const int c0 = seg * 31;
        const int cn = (seg == 3) ? 32 : 31;
        float s = 0.f;
        #pragma unroll 31
        for (int c = 0; c < cn; c++)
            s += g_part[((size_t)((c0 + c) * 8 + b)) * Dv + jg + j];
        xr[seg][j] = s;
    }
    __syncthreads();
    if (seg == 0)
        xs[j] = xr[0][j] + xr[1][j] + xr[2][j] + xr[3][j];
    __syncthreads();

    {
        float acc = 0.f;
        #pragma unroll
        for (int jj = 0; jj < 16; jj++) {
            int jl = seg * 16 + jj;
            acc += xs[jl] * Wv[(size_t)(jg + jl) * 64 + j];
        }
        p[seg][j] = acc;
    }
    __syncthreads();
    if (seg == 0)
        g_vsump[(jb * 8 + b) * 64 + j] = p[0][j] + p[1][j] + p[2][j] + p[3][j];
}

// ---------------------------------------------------------------------------
// 3) row[b,n] = bo[n] + sum_m vs[b, m&63] * Wo[m,n]. grid 32, 256 threads.
// ---------------------------------------------------------------------------
__global__ void __launch_bounds__(256)
row_kernel(const float* __restrict__ Wo, const float* __restrict__ bv,
           const float* __restrict__ bo)
{
    __shared__ float vs[8 * 64];
    __shared__ float part[8][8][32];

    const int n0   = blockIdx.x * 32;
    const int tid  = threadIdx.x;
    const int lane = tid & 31;
    const int wid  = tid >> 5;
    const int n    = n0 + lane;

    #pragma unroll
    for (int i = tid; i < 512; i += 256) {
        int d = i & 63;
        float s = (float)Tv * bv[d];
        #pragma unroll
        for (int jb = 0; jb < 16; jb++)
            s += g_vsump[jb * 512 + i];
        vs[i] = s;
    }
    __syncthreads();

    float acc[8] = {};
    const int mbase = wid * 128;
    #pragma unroll 8
    for (int mm = 0; mm < 64; mm++) {
        float w1 = Wo[(size_t)(mbase + mm) * Dv + n];
        float w2 = Wo[(size_t)(mbase + mm + 64) * Dv + n];
        float w  = w1 + w2;
        #pragma unroll
        for (int b = 0; b < 8; b++)
            acc[b] = fmaf(vs[b * 64 + mm], w, acc[b]);
    }
    #pragma unroll
    for (int b = 0; b < 8; b++)
        part[wid][b][lane] = acc[b];
    __syncthreads();

    {
        int b = wid;
        float s = bo[n];
        #pragma unroll
        for (int w = 0; w < 8; w++)
            s += part[w][b][lane];
        g_row[b * Dv + n] = s;
    }
}

// ---------------------------------------------------------------------------
// 4) Broadcast: grid (125, 8), 256 threads. One float4/thread from g_row,
//    8 streaming STG.128.CS rows (evict-first: don't pollute L2).
// ---------------------------------------------------------------------------
__global__ void __launch_bounds__(256)
bcast_kernel(float* __restrict__ out)
{
    const int chunk = blockIdx.x;
    const int b     = blockIdx.y;

    float4 v = ((const float4*)g_row)[b * 256 + threadIdx.x];
    float4* op = (float4*)out + ((size_t)b * Tv + chunk * 8) * 256 + threadIdx.x;
    stcs128(op + 0 * 256, v);  stcs128(op + 1 * 256, v);
    stcs128(op + 2 * 256, v);  stcs128(op + 3 * 256, v);
    stcs128(op + 4 * 256, v);  stcs128(op + 5 * 256, v);
    stcs128(op + 6 * 256, v);  stcs128(op + 7 * 256, v);
}

// ---------------------------------------------------------------------------
extern "C" void kernel_launch(void* const* d_in, const int* in_sizes, int n_in,
                              void* d_out, int out_size)
{
    const float* x  = (const float*)d_in[0];
    const float* Wv = (const float*)d_in[5];
    const float* bv = (const float*)d_in[6];
    const float* Wo = (const float*)d_in[7];
    const float* bo = (const float*)d_in[8];
    float* out = (float*)d_out;

    xsum_part_kernel<<<dim3(NCHUNK, 8), 256>>>(x);
    vsum_part_kernel<<<dim3(8, 16), 256>>>(Wv);
    row_kernel<<<32, 256>>>(Wo, bv, bo);
    bcast_kernel<<<dim3(NCHUNK, 8), 256>>>(out);
}